// round 1
// baseline (speedup 1.0000x reference)
#include <cuda_runtime.h>
#include <cuda_fp16.h>

#define N 8192
#define NBLK_FIN 8192

// Scratch (allocation-free rule: __device__ globals)
__device__ __half g_K [(size_t)N * N];   // K  = exp(-C), row-major
__device__ __half g_KT[(size_t)N * N];   // K^T, row-major (= column-major K)
__device__ float  g_u[N];
__device__ float  g_v[N];
__device__ float  g_part[NBLK_FIN];

// ---------------------------------------------------------------------------
// Setup: K = exp(-C) in fp16 (row-major) + transposed copy, 32x32 smem tiles.
// ---------------------------------------------------------------------------
__global__ void __launch_bounds__(256) setup_kernel(const float* __restrict__ C) {
    __shared__ __half tile[32][34];           // padded: conflict-light transpose
    const int bx = blockIdx.x;                // tile column index
    const int by = blockIdx.y;                // tile row index
    const int tx = threadIdx.x;               // 0..31
    const int ty = threadIdx.y;               // 0..7

    const int col = bx * 32 + tx;
    #pragma unroll
    for (int r = ty; r < 32; r += 8) {
        const int row = by * 32 + r;
        const float c = C[(size_t)row * N + col];
        const __half h = __float2half_rn(__expf(-c));
        g_K[(size_t)row * N + col] = h;
        tile[r][tx] = h;
    }
    __syncthreads();
    #pragma unroll
    for (int rr = ty; rr < 32; rr += 8) {
        // KT[bx*32+rr][by*32+tx] = K[by*32+tx][bx*32+rr]
        g_KT[(size_t)(bx * 32 + rr) * N + by * 32 + tx] = tile[tx][rr];
    }
}

__global__ void init_uv_kernel() {
    const int i = blockIdx.x * blockDim.x + threadIdx.x;
    if (i < N) { g_u[i] = 1.0f; g_v[i] = 1.0f; }
}

// ---------------------------------------------------------------------------
// y[r] = 1 / (N * dot(M[r,:], x)).  One warp per row, 8 rows per block.
// x staged in smem (32 KB) so the per-block x traffic never leaves the SM.
// ---------------------------------------------------------------------------
__global__ void __launch_bounds__(256) gemv_recip_kernel(
    const __half* __restrict__ M,
    const float*  __restrict__ x,
    float*        __restrict__ y)
{
    __shared__ float xs[N];                   // 32 KB
    {
        const float4* x4  = (const float4*)x;
        float4*       xs4 = (float4*)xs;
        #pragma unroll
        for (int i = threadIdx.x; i < N / 4; i += 256) xs4[i] = x4[i];
    }
    __syncthreads();

    const int warp = threadIdx.x >> 5;
    const int lane = threadIdx.x & 31;
    const int row  = blockIdx.x * 8 + warp;

    const uint4* Mr = (const uint4*)(M + (size_t)row * N);   // 8 halves / uint4
    const float4* xs4 = (const float4*)xs;

    float sum = 0.0f;
    #pragma unroll 8
    for (int k = 0; k < 32; ++k) {
        const int idx = lane + k * 32;        // uint4 index within row
        const uint4 q  = Mr[idx];
        const float4 v0 = xs4[idx * 2 + 0];
        const float4 v1 = xs4[idx * 2 + 1];
        const __half2* h2 = (const __half2*)&q;
        const float2 a0 = __half22float2(h2[0]);
        const float2 a1 = __half22float2(h2[1]);
        const float2 a2 = __half22float2(h2[2]);
        const float2 a3 = __half22float2(h2[3]);
        sum = fmaf(a0.x, v0.x, sum);
        sum = fmaf(a0.y, v0.y, sum);
        sum = fmaf(a1.x, v0.z, sum);
        sum = fmaf(a1.y, v0.w, sum);
        sum = fmaf(a2.x, v1.x, sum);
        sum = fmaf(a2.y, v1.y, sum);
        sum = fmaf(a3.x, v1.z, sum);
        sum = fmaf(a3.y, v1.w, sum);
    }
    #pragma unroll
    for (int off = 16; off > 0; off >>= 1)
        sum += __shfl_down_sync(0xffffffffu, sum, off);

    if (lane == 0) y[row] = 1.0f / (8192.0f * sum);
}

// ---------------------------------------------------------------------------
// Final: per-block partials of  W = sum_ij u_i * K_ij * v_j * C_ij.
// Uses stored fp16 K (re-running exp would be MUFU-bound: ~0.46 ms).
// ---------------------------------------------------------------------------
__global__ void __launch_bounds__(256) final_partial_kernel(const float* __restrict__ C) {
    float acc = 0.0f;
    const size_t total8 = (size_t)N * N / 8;
    const size_t stride = (size_t)gridDim.x * 256;
    for (size_t t = (size_t)blockIdx.x * 256 + threadIdx.x; t < total8; t += stride) {
        const size_t e = t * 8;
        const int i = (int)(e >> 13);
        const int j = (int)(e & (N - 1));
        const float  ui = g_u[i];
        const uint4  kq = *(const uint4*)(g_K + e);
        const float4 c0 = *(const float4*)(C + e);
        const float4 c1 = *(const float4*)(C + e + 4);
        const float4 w0 = *(const float4*)(g_v + j);
        const float4 w1 = *(const float4*)(g_v + j + 4);
        const __half2* h2 = (const __half2*)&kq;
        const float2 a0 = __half22float2(h2[0]);
        const float2 a1 = __half22float2(h2[1]);
        const float2 a2 = __half22float2(h2[2]);
        const float2 a3 = __half22float2(h2[3]);
        float s = 0.0f;
        s = fmaf(a0.x * w0.x, c0.x, s);
        s = fmaf(a0.y * w0.y, c0.y, s);
        s = fmaf(a1.x * w0.z, c0.z, s);
        s = fmaf(a1.y * w0.w, c0.w, s);
        s = fmaf(a2.x * w1.x, c1.x, s);
        s = fmaf(a2.y * w1.y, c1.y, s);
        s = fmaf(a3.x * w1.z, c1.z, s);
        s = fmaf(a3.y * w1.w, c1.w, s);
        acc = fmaf(ui, s, acc);
    }
    __shared__ float sh[256];
    sh[threadIdx.x] = acc;
    __syncthreads();
    #pragma unroll
    for (int s = 128; s > 0; s >>= 1) {
        if (threadIdx.x < s) sh[threadIdx.x] += sh[threadIdx.x + s];
        __syncthreads();
    }
    if (threadIdx.x == 0) g_part[blockIdx.x] = sh[0];
}

// Deterministic second-stage reduction (no float atomics anywhere).
__global__ void __launch_bounds__(256) final_reduce_kernel(float* __restrict__ out) {
    float s = 0.0f;
    for (int i = threadIdx.x; i < NBLK_FIN; i += 256) s += g_part[i];
    __shared__ float sh[256];
    sh[threadIdx.x] = s;
    __syncthreads();
    #pragma unroll
    for (int k = 128; k > 0; k >>= 1) {
        if (threadIdx.x < k) sh[threadIdx.x] += sh[threadIdx.x + k];
        __syncthreads();
    }
    if (threadIdx.x == 0) out[0] = sh[0];
}

// ---------------------------------------------------------------------------
extern "C" void kernel_launch(void* const* d_in, const int* in_sizes, int n_in,
                              void* d_out, int out_size) {
    const float* C = (const float*)d_in[0];
    float* out = (float*)d_out;

    __half *K, *KT;
    float *u, *v;
    cudaGetSymbolAddress((void**)&K,  g_K);
    cudaGetSymbolAddress((void**)&KT, g_KT);
    cudaGetSymbolAddress((void**)&u,  g_u);
    cudaGetSymbolAddress((void**)&v,  g_v);

    setup_kernel<<<dim3(N / 32, N / 32), dim3(32, 8)>>>(C);
    init_uv_kernel<<<(N + 255) / 256, 256>>>();

    for (int it = 0; it < 100; ++it) {
        gemv_recip_kernel<<<N / 8, 256>>>(KT, u, v);   // v = 1/(m * K^T u)
        gemv_recip_kernel<<<N / 8, 256>>>(K,  v, u);   // u = 1/(n * K v)
    }

    final_partial_kernel<<<NBLK_FIN, 256>>>(C);
    final_reduce_kernel<<<1, 256>>>(out);
}